// round 12
// baseline (speedup 1.0000x reference)
#include <cuda_runtime.h>
#include <cstdint>

#define C_IN  32
#define C_OUT 64
#define KNUM  8
#define TILE  1024
#define NBUF  4
#define NPAIR 8
#define EPS   1e-5f

__device__ float g_sum[C_OUT];
__device__ float g_sumsq[C_OUT];
__device__ float g_a[C_OUT];
__device__ float g_b[C_OUT];

// xs first: extern-shared base is 16B+ aligned (cp.async 16B dst requirement).
struct ConvSmem {
    float    xs[NPAIR][NBUF][16][C_IN];   // 64 KB staged x rows (XOR-swizzled)
    uint16_t bins[KNUM][TILE];            // 16 KB tile-local voxel indices
    int      o16[NPAIR][NBUF][16];        // 2 KB  staged out-row indices
    int      cnts[KNUM + 2];
    int      work_off[KNUM + 1];          // chunk-offset prefix per bin
};

__device__ __forceinline__ uint32_t f2tf32(float f) {
    uint32_t r;
    asm("cvt.rna.tf32.f32 %0, %1;" : "=r"(r) : "f"(f));
    return r;
}

// ---------------------------------------------------------------------------
// Pass A: sparse conv + scatter via tf32 mma.sync (m16n8k8).
// 512 threads = 8 warp-pairs, 2 CTAs/SM. Chunks of 16 voxels from ALL bins
// form a shared worklist; pair p takes items p, p+8, ... (perfect balance).
// Warp h of a pair computes output channels [32h, 32h+32); B fragments are
// loaded from global W per chunk (L1-resident). x rows cp.async-staged into
// the pair's ring of 4 buffers at prefetch distance 2 (the R11 NBUF=2 ring
// raced: warp A overwrote the buffer warp B was still reading — distance 2
// keeps a pair barrier between last-read and overwrite).
// ---------------------------------------------------------------------------
__global__ void __launch_bounds__(512, 2)
conv_scatter(const float* __restrict__ x,
             const float* __restrict__ W,
             const int*   __restrict__ kidx,
             const int*   __restrict__ oidx,
             float*       __restrict__ out,
             int n)
{
    extern __shared__ char smem_raw[];
    ConvSmem* sm = reinterpret_cast<ConvSmem*>(smem_raw);

    const int tid  = threadIdx.x;
    const int lane = tid & 31;
    const int wid  = tid >> 5;       // 0..15
    const int pair = wid >> 1;       // 0..7
    const int h    = wid & 1;        // channel half

    if (blockIdx.x == 0 && tid < C_OUT) { g_sum[tid] = 0.f; g_sumsq[tid] = 0.f; }

    const int rl = lane >> 2;        // 0..7
    const int e  = lane & 3;         // 0..3

    // ---- Binning (warp-aggregated, tile-local uint16 indices) ----
    const int tileBase = blockIdx.x * TILE;
    if (tid < KNUM + 2) sm->cnts[tid] = 0;
    __syncthreads();

    #pragma unroll
    for (int u = 0; u < TILE / 512; ++u) {
        int  loc   = u * 512 + tid;
        int  i     = tileBase + loc;
        bool valid = (i < n);
        int  k     = valid ? kidx[i] : KNUM;
        unsigned mask   = __match_any_sync(0xffffffffu, k);
        int      leader = __ffs(mask) - 1;
        int      rank   = __popc(mask & ((1u << lane) - 1u));
        int      base   = 0;
        if (lane == leader) base = atomicAdd(&sm->cnts[k], __popc(mask));
        base = __shfl_sync(0xffffffffu, base, leader);
        if (valid) sm->bins[k][base + rank] = (uint16_t)loc;
    }
    __syncthreads();

    // ---- Worklist: exclusive prefix of per-bin chunk counts ----
    if (tid == 0) {
        int off = 0;
        #pragma unroll
        for (int j = 0; j < KNUM; ++j) {
            sm->work_off[j] = off;
            off += (sm->cnts[j] + 15) >> 4;
        }
        sm->work_off[KNUM] = off;
    }
    __syncthreads();
    const int total_chunks = sm->work_off[KNUM];

    const uint32_t xs_smem =
        (uint32_t)__cvta_generic_to_shared(&sm->xs[pair][0][0][0]);

    // Decode work item w -> (bin jj, voxel base).
    auto decode = [&](int w, int& jj, int& base) {
        jj = 0;
        #pragma unroll
        for (int t = 0; t < KNUM - 1; ++t) jj += (w >= sm->work_off[t + 1]);
        base = (w - sm->work_off[jj]) << 4;
    };

    // Stage chunk w into pair buffer 'buf'. Both warps stage their 8 rows
    // (rows 8h..8h+7); row s stored col-swizzled c ^ ((s&7)<<2).
    // ALWAYS commits a group (possibly empty) to keep wait_group counting.
    auto stage = [&](int w, int buf) {
        if (w < total_chunks) {
            int jj, base; decode(w, jj, base);
            const int cntj = sm->cnts[jj];
            const int s    = 8 * h + (lane >> 2);
            int idx = base + s;
            if (idx < cntj) {
                int i = tileBase + (int)sm->bins[jj][idx];
                #pragma unroll
                for (int t = 0; t < 2; ++t) {
                    int g = (lane & 3) + 4 * t;       // 16B group
                    const float* src = x + (size_t)i * C_IN + g * 4;
                    uint32_t fc  = (uint32_t)((g * 4) ^ ((s & 7) << 2));
                    uint32_t dst = xs_smem +
                        (uint32_t)(buf * 16 * C_IN + s * C_IN + fc) * 4u;
                    asm volatile("cp.async.ca.shared.global [%0], [%1], 16;"
                                 :: "r"(dst), "l"(src));
                }
            }
            if (h == 0 && lane < 16) {
                int idx2 = base + lane;
                sm->o16[pair][buf][lane] =
                    (idx2 < cntj) ? oidx[tileBase + (int)sm->bins[jj][idx2]] : 0;
            }
        }
        asm volatile("cp.async.commit_group;");
    };

    // Prologue: chunks pair, pair+8 into buffers 0, 1.
    stage(pair, 0);
    stage(pair + NPAIR, 1);

    for (int it = 0, w = pair; w < total_chunks; ++it, w += NPAIR) {
        const int buf = it & 3;
        stage(w + 2 * NPAIR, (it + 2) & 3);
        asm volatile("cp.async.wait_group 2;");
        asm volatile("bar.sync %0, 64;" :: "r"(pair + 1));

        int jj, base; decode(w, jj, base);
        const int cntj = sm->cnts[jj];

        const int  oa = sm->o16[pair][buf][rl];
        const int  ob = sm->o16[pair][buf][rl + 8];
        const bool va = (base + rl)     < cntj;
        const bool vb = (base + rl + 8) < cntj;

        float c[4][4];
        #pragma unroll
        for (int nt = 0; nt < 4; ++nt)
            c[nt][0] = c[nt][1] = c[nt][2] = c[nt][3] = 0.f;

        const float* xb = &sm->xs[pair][buf][0][0];
        const float* Wj = W + jj * (C_IN * C_OUT);
        #pragma unroll
        for (int kt = 0; kt < 4; ++kt) {
            int c0 = (kt * 8 + e)     ^ (rl << 2);
            int c4 = (kt * 8 + 4 + e) ^ (rl << 2);
            uint32_t a0 = f2tf32(xb[rl * C_IN + c0]);
            uint32_t a1 = f2tf32(xb[(rl + 8) * C_IN + c0]);
            uint32_t a2 = f2tf32(xb[rl * C_IN + c4]);
            uint32_t a3 = f2tf32(xb[(rl + 8) * C_IN + c4]);
            #pragma unroll
            for (int nt = 0; nt < 4; ++nt) {
                int col = h * 32 + nt * 8 + rl;
                uint32_t b0 = f2tf32(Wj[(kt * 8 + e)     * C_OUT + col]);
                uint32_t b1 = f2tf32(Wj[(kt * 8 + e + 4) * C_OUT + col]);
                asm volatile(
                    "mma.sync.aligned.m16n8k8.row.col.f32.tf32.tf32.f32 "
                    "{%0,%1,%2,%3}, {%4,%5,%6,%7}, {%8,%9}, {%0,%1,%2,%3};"
                    : "+f"(c[nt][0]), "+f"(c[nt][1]),
                      "+f"(c[nt][2]), "+f"(c[nt][3])
                    : "r"(a0), "r"(a1), "r"(a2), "r"(a3),
                      "r"(b0), "r"(b1));
            }
        }

        #pragma unroll
        for (int nt = 0; nt < 4; ++nt) {
            int coloff = h * 32 + nt * 8 + (e << 1);
            if (va) atomicAdd((float2*)(out + (size_t)oa * C_OUT + coloff),
                              make_float2(c[nt][0], c[nt][1]));
            if (vb) atomicAdd((float2*)(out + (size_t)ob * C_OUT + coloff),
                              make_float2(c[nt][2], c[nt][3]));
        }
    }
    asm volatile("cp.async.wait_group 0;");
}

// ---------------------------------------------------------------------------
// Pass B: per-channel sum / sum-of-squares, float4 + unroll-4.
// ---------------------------------------------------------------------------
__global__ void stats_pass(const float4* __restrict__ out4, int n4)
{
    float4 s  = make_float4(0.f, 0.f, 0.f, 0.f);
    float4 s2 = make_float4(0.f, 0.f, 0.f, 0.f);
    const int start  = blockIdx.x * blockDim.x + threadIdx.x;
    const int stride = blockDim.x * gridDim.x;   // multiple of 16
    for (int i = start; i < n4; i += 4 * stride) {
        #pragma unroll
        for (int u = 0; u < 4; ++u) {
            int jx = i + u * stride;
            if (jx < n4) {
                float4 v = out4[jx];
                s.x += v.x; s.y += v.y; s.z += v.z; s.w += v.w;
                s2.x = fmaf(v.x, v.x, s2.x);
                s2.y = fmaf(v.y, v.y, s2.y);
                s2.z = fmaf(v.z, v.z, s2.z);
                s2.w = fmaf(v.w, v.w, s2.w);
            }
        }
    }

    __shared__ float sh1[C_OUT], sh2[C_OUT];
    if (threadIdx.x < C_OUT) { sh1[threadIdx.x] = 0.f; sh2[threadIdx.x] = 0.f; }
    __syncthreads();
    const int cg = (start & 15) * 4;
    atomicAdd(&sh1[cg + 0], s.x);  atomicAdd(&sh1[cg + 1], s.y);
    atomicAdd(&sh1[cg + 2], s.z);  atomicAdd(&sh1[cg + 3], s.w);
    atomicAdd(&sh2[cg + 0], s2.x); atomicAdd(&sh2[cg + 1], s2.y);
    atomicAdd(&sh2[cg + 2], s2.z); atomicAdd(&sh2[cg + 3], s2.w);
    __syncthreads();
    if (threadIdx.x < C_OUT) {
        atomicAdd(&g_sum[threadIdx.x],   sh1[threadIdx.x]);
        atomicAdd(&g_sumsq[threadIdx.x], sh2[threadIdx.x]);
    }
}

// ---------------------------------------------------------------------------
// Pass C: finalize BN affine (conv bias cancels algebraically).
// ---------------------------------------------------------------------------
__global__ void finalize_stats(const float* __restrict__ gamma,
                               const float* __restrict__ beta,
                               float inv_n)
{
    const int c = threadIdx.x;
    float mean = g_sum[c] * inv_n;
    float var  = g_sumsq[c] * inv_n - mean * mean;
    float a    = gamma[c] * rsqrtf(var + EPS);
    g_a[c] = a;
    g_b[c] = fmaf(-mean, a, beta[c]);
}

// ---------------------------------------------------------------------------
// Pass D: in-place normalize + ReLU, float4 + unroll-2.
// ---------------------------------------------------------------------------
__global__ void norm_relu(float4* __restrict__ out4, int n4)
{
    const int start  = blockIdx.x * blockDim.x + threadIdx.x;
    const int stride = blockDim.x * gridDim.x;   // multiple of 16
    const int cg = (start & 15) * 4;
    const float4 a = *(const float4*)&g_a[cg];
    const float4 b = *(const float4*)&g_b[cg];
    for (int i = start; i < n4; i += 2 * stride) {
        float4 v0 = out4[i];
        int jx = i + stride;
        bool has1 = (jx < n4);
        float4 v1 = has1 ? out4[jx] : make_float4(0.f, 0.f, 0.f, 0.f);
        v0.x = fmaxf(fmaf(v0.x, a.x, b.x), 0.f);
        v0.y = fmaxf(fmaf(v0.y, a.y, b.y), 0.f);
        v0.z = fmaxf(fmaf(v0.z, a.z, b.z), 0.f);
        v0.w = fmaxf(fmaf(v0.w, a.w, b.w), 0.f);
        out4[i] = v0;
        if (has1) {
            v1.x = fmaxf(fmaf(v1.x, a.x, b.x), 0.f);
            v1.y = fmaxf(fmaf(v1.y, a.y, b.y), 0.f);
            v1.z = fmaxf(fmaf(v1.z, a.z, b.z), 0.f);
            v1.w = fmaxf(fmaf(v1.w, a.w, b.w), 0.f);
            out4[jx] = v1;
        }
    }
}

// ---------------------------------------------------------------------------
// Launch. Inputs: x, W, bias, gamma, beta, k_idx, out_idx, num_out.
// ---------------------------------------------------------------------------
extern "C" void kernel_launch(void* const* d_in, const int* in_sizes, int n_in,
                              void* d_out, int out_size)
{
    const float* x     = (const float*)d_in[0];
    const float* W     = (const float*)d_in[1];
    const float* gamma = (const float*)d_in[3];
    const float* beta  = (const float*)d_in[4];
    const int*   kidx  = (const int*)d_in[5];
    const int*   oidx  = (const int*)d_in[6];

    const int n       = in_sizes[0] / C_IN;
    const int total   = out_size;               // num_out * 64
    const int num_out = total / C_OUT;
    const int n4      = total / 4;

    const int smem_bytes = (int)sizeof(ConvSmem);   // ~84 KB
    cudaFuncSetAttribute(conv_scatter,
                         cudaFuncAttributeMaxDynamicSharedMemorySize,
                         smem_bytes);

    cudaMemsetAsync(d_out, 0, (size_t)total * sizeof(float), 0);

    const int tiles = (n + TILE - 1) / TILE;
    conv_scatter<<<tiles, 512, smem_bytes>>>(x, W, kidx, oidx, (float*)d_out, n);
    stats_pass<<<1184, 256>>>((const float4*)d_out, n4);
    finalize_stats<<<1, C_OUT>>>(gamma, beta, 1.0f / (float)num_out);
    norm_relu<<<1184, 256>>>((float4*)d_out, n4);
}

// round 13
// speedup vs baseline: 1.1336x; 1.1336x over previous
#include <cuda_runtime.h>
#include <cstdint>

#define C_IN  32
#define C_OUT 64
#define KNUM  8
#define TILE  1024
#define NBUF  4
#define NQUAD 4
#define EPS   1e-5f

__device__ float g_sum[C_OUT];
__device__ float g_sumsq[C_OUT];
__device__ float g_a[C_OUT];
__device__ float g_b[C_OUT];

// xs first: extern-shared base is 16B+ aligned (cp.async 16B dst requirement).
struct ConvSmem {
    float    xs[NQUAD][NBUF][16][C_IN];   // 32 KB staged x rows (XOR-swizzled)
    uint16_t bins[KNUM][TILE];            // 16 KB tile-local voxel indices
    int      o16[NQUAD][NBUF][16];        // 1 KB  staged out-row indices
    int      cnts[KNUM + 2];
};

__device__ __forceinline__ uint32_t f2tf32(float f) {
    uint32_t r;
    asm("cvt.rna.tf32.f32 %0, %1;" : "=r"(r) : "f"(f));
    return r;
}

// ---------------------------------------------------------------------------
// Pass A: sparse conv + scatter via tf32 mma.sync (m16n8k8).
// 512 threads = 4 warp-QUADS, 2 CTAs/SM (the R10 pair design was 1 CTA/SM).
// Quad q processes bins q and q+4 sequentially; warp w of a quad computes
// output channels [16w, 16w+16), so W fragments are only 16 regs/thread and
// the whole kernel fits 2 CTAs/SM for 2x the warps hiding RED/L2 latency.
// x rows cp.async-staged into the quad's ring of 4 buffers, prefetch
// distance 2 (proven safe in R10); scatter via float2 RED with validity
// predicates. W fragments live in registers; reloaded once at the bin switch.
// ---------------------------------------------------------------------------
__global__ void __launch_bounds__(512, 2)
conv_scatter(const float* __restrict__ x,
             const float* __restrict__ W,
             const int*   __restrict__ kidx,
             const int*   __restrict__ oidx,
             float*       __restrict__ out,
             int n)
{
    extern __shared__ char smem_raw[];
    ConvSmem* sm = reinterpret_cast<ConvSmem*>(smem_raw);

    const int tid  = threadIdx.x;
    const int lane = tid & 31;
    const int wid  = tid >> 5;       // 0..15
    const int quad = wid >> 2;       // 0..3
    const int w4   = wid & 3;        // warp within quad: channels [16*w4, +16)

    if (blockIdx.x == 0 && tid < C_OUT) { g_sum[tid] = 0.f; g_sumsq[tid] = 0.f; }

    const int rl = lane >> 2;        // 0..7
    const int e  = lane & 3;         // 0..3

    // ---- Binning (warp-aggregated, tile-local uint16 indices) ----
    const int tileBase = blockIdx.x * TILE;
    if (tid < KNUM + 2) sm->cnts[tid] = 0;
    __syncthreads();

    #pragma unroll
    for (int u = 0; u < TILE / 512; ++u) {
        int  loc   = u * 512 + tid;
        int  i     = tileBase + loc;
        bool valid = (i < n);
        int  k     = valid ? kidx[i] : KNUM;
        unsigned mask   = __match_any_sync(0xffffffffu, k);
        int      leader = __ffs(mask) - 1;
        int      rank   = __popc(mask & ((1u << lane) - 1u));
        int      base   = 0;
        if (lane == leader) base = atomicAdd(&sm->cnts[k], __popc(mask));
        base = __shfl_sync(0xffffffffu, base, leader);
        if (valid) sm->bins[k][base + rank] = (uint16_t)loc;
    }
    __syncthreads();

    const int cnt_a = sm->cnts[quad];
    const int cnt_b = sm->cnts[quad + NQUAD];
    const int na    = (cnt_a + 15) >> 4;
    const int nb    = (cnt_b + 15) >> 4;
    const int ntot  = na + nb;
    if (ntot == 0) return;

    const uint32_t xs_smem =
        (uint32_t)__cvta_generic_to_shared(&sm->xs[quad][0][0][0]);

    // decode chunk t -> (bin jj, bin-local voxel base, bin count)
    auto decode = [&](int t, int& jj, int& base, int& cntj) {
        if (t < na) { jj = quad;         base = t * 16;        cntj = cnt_a; }
        else        { jj = quad + NQUAD; base = (t - na) * 16; cntj = cnt_b; }
    };

    // Stage chunk t into quad buffer 'buf'. Warp w4 stages rows 4*w4..4*w4+3;
    // each lane issues ONE 16B cp.async: row s = 4*w4 + (lane>>3), group
    // g = lane&7, stored col-swizzled (g*4) ^ ((s&7)<<2).
    // ALWAYS commits a group (possibly empty) to keep wait_group counting.
    auto stage = [&](int t, int buf) {
        if (t < ntot) {
            int jj, base, cntj; decode(t, jj, base, cntj);
            const int s   = 4 * w4 + (lane >> 3);
            const int idx = base + s;
            if (idx < cntj) {
                int i = tileBase + (int)sm->bins[jj][idx];
                int g = lane & 7;
                const float* src = x + (size_t)i * C_IN + g * 4;
                uint32_t fc  = (uint32_t)((g * 4) ^ ((s & 7) << 2));
                uint32_t dst = xs_smem +
                    (uint32_t)(buf * 16 * C_IN + s * C_IN + fc) * 4u;
                asm volatile("cp.async.ca.shared.global [%0], [%1], 16;"
                             :: "r"(dst), "l"(src));
            }
            if (w4 == 0 && lane < 16) {
                int idx2 = base + lane;
                sm->o16[quad][buf][lane] =
                    (idx2 < cntj) ? oidx[tileBase + (int)sm->bins[jj][idx2]] : 0;
            }
        }
        asm volatile("cp.async.commit_group;");
    };

    // W fragments for current bin: bf[kt][nt][2], cols 16*w4 + nt*8 + rl.
    uint32_t bf[4][2][2];
    int cur_bin = -1;
    auto load_bf = [&](int jj) {
        const float* Wj = W + jj * (C_IN * C_OUT);
        #pragma unroll
        for (int kt = 0; kt < 4; ++kt)
            #pragma unroll
            for (int nt = 0; nt < 2; ++nt) {
                int col = 16 * w4 + nt * 8 + rl;
                bf[kt][nt][0] = f2tf32(Wj[(kt * 8 + e)     * C_OUT + col]);
                bf[kt][nt][1] = f2tf32(Wj[(kt * 8 + e + 4) * C_OUT + col]);
            }
    };

    // Prologue: chunks 0, 1 into buffers 0, 1.
    stage(0, 0);
    stage(1, 1);

    for (int t = 0; t < ntot; ++t) {
        const int buf = t & 3;
        stage(t + 2, (t + 2) & 3);
        asm volatile("cp.async.wait_group 2;");
        asm volatile("bar.sync %0, 128;" :: "r"(quad + 1));

        int jj, base, cntj; decode(t, jj, base, cntj);
        if (jj != cur_bin) { load_bf(jj); cur_bin = jj; }

        const int  oa = sm->o16[quad][buf][rl];
        const int  ob = sm->o16[quad][buf][rl + 8];
        const bool va = (base + rl)     < cntj;
        const bool vb = (base + rl + 8) < cntj;

        float c[2][4];
        #pragma unroll
        for (int nt = 0; nt < 2; ++nt)
            c[nt][0] = c[nt][1] = c[nt][2] = c[nt][3] = 0.f;

        const float* xb = &sm->xs[quad][buf][0][0];
        #pragma unroll
        for (int kt = 0; kt < 4; ++kt) {
            int c0 = (kt * 8 + e)     ^ (rl << 2);
            int c4 = (kt * 8 + 4 + e) ^ (rl << 2);
            uint32_t a0 = f2tf32(xb[rl * C_IN + c0]);
            uint32_t a1 = f2tf32(xb[(rl + 8) * C_IN + c0]);
            uint32_t a2 = f2tf32(xb[rl * C_IN + c4]);
            uint32_t a3 = f2tf32(xb[(rl + 8) * C_IN + c4]);
            #pragma unroll
            for (int nt = 0; nt < 2; ++nt) {
                asm volatile(
                    "mma.sync.aligned.m16n8k8.row.col.f32.tf32.tf32.f32 "
                    "{%0,%1,%2,%3}, {%4,%5,%6,%7}, {%8,%9}, {%0,%1,%2,%3};"
                    : "+f"(c[nt][0]), "+f"(c[nt][1]),
                      "+f"(c[nt][2]), "+f"(c[nt][3])
                    : "r"(a0), "r"(a1), "r"(a2), "r"(a3),
                      "r"(bf[kt][nt][0]), "r"(bf[kt][nt][1]));
            }
        }

        #pragma unroll
        for (int nt = 0; nt < 2; ++nt) {
            int coloff = 16 * w4 + nt * 8 + (e << 1);
            if (va) atomicAdd((float2*)(out + (size_t)oa * C_OUT + coloff),
                              make_float2(c[nt][0], c[nt][1]));
            if (vb) atomicAdd((float2*)(out + (size_t)ob * C_OUT + coloff),
                              make_float2(c[nt][2], c[nt][3]));
        }
    }
    asm volatile("cp.async.wait_group 0;");
}

// ---------------------------------------------------------------------------
// Pass B: per-channel sum / sum-of-squares, float4 + unroll-4.
// ---------------------------------------------------------------------------
__global__ void stats_pass(const float4* __restrict__ out4, int n4)
{
    float4 s  = make_float4(0.f, 0.f, 0.f, 0.f);
    float4 s2 = make_float4(0.f, 0.f, 0.f, 0.f);
    const int start  = blockIdx.x * blockDim.x + threadIdx.x;
    const int stride = blockDim.x * gridDim.x;   // multiple of 16
    for (int i = start; i < n4; i += 4 * stride) {
        #pragma unroll
        for (int u = 0; u < 4; ++u) {
            int jx = i + u * stride;
            if (jx < n4) {
                float4 v = out4[jx];
                s.x += v.x; s.y += v.y; s.z += v.z; s.w += v.w;
                s2.x = fmaf(v.x, v.x, s2.x);
                s2.y = fmaf(v.y, v.y, s2.y);
                s2.z = fmaf(v.z, v.z, s2.z);
                s2.w = fmaf(v.w, v.w, s2.w);
            }
        }
    }

    __shared__ float sh1[C_OUT], sh2[C_OUT];
    if (threadIdx.x < C_OUT) { sh1[threadIdx.x] = 0.f; sh2[threadIdx.x] = 0.f; }
    __syncthreads();
    const int cg = (start & 15) * 4;
    atomicAdd(&sh1[cg + 0], s.x);  atomicAdd(&sh1[cg + 1], s.y);
    atomicAdd(&sh1[cg + 2], s.z);  atomicAdd(&sh1[cg + 3], s.w);
    atomicAdd(&sh2[cg + 0], s2.x); atomicAdd(&sh2[cg + 1], s2.y);
    atomicAdd(&sh2[cg + 2], s2.z); atomicAdd(&sh2[cg + 3], s2.w);
    __syncthreads();
    if (threadIdx.x < C_OUT) {
        atomicAdd(&g_sum[threadIdx.x],   sh1[threadIdx.x]);
        atomicAdd(&g_sumsq[threadIdx.x], sh2[threadIdx.x]);
    }
}

// ---------------------------------------------------------------------------
// Pass C: finalize BN affine (conv bias cancels algebraically).
// ---------------------------------------------------------------------------
__global__ void finalize_stats(const float* __restrict__ gamma,
                               const float* __restrict__ beta,
                               float inv_n)
{
    const int c = threadIdx.x;
    float mean = g_sum[c] * inv_n;
    float var  = g_sumsq[c] * inv_n - mean * mean;
    float a    = gamma[c] * rsqrtf(var + EPS);
    g_a[c] = a;
    g_b[c] = fmaf(-mean, a, beta[c]);
}

// ---------------------------------------------------------------------------
// Pass D: in-place normalize + ReLU, float4 + unroll-2.
// ---------------------------------------------------------------------------
__global__ void norm_relu(float4* __restrict__ out4, int n4)
{
    const int start  = blockIdx.x * blockDim.x + threadIdx.x;
    const int stride = blockDim.x * gridDim.x;   // multiple of 16
    const int cg = (start & 15) * 4;
    const float4 a = *(const float4*)&g_a[cg];
    const float4 b = *(const float4*)&g_b[cg];
    for (int i = start; i < n4; i += 2 * stride) {
        float4 v0 = out4[i];
        int jx = i + stride;
        bool has1 = (jx < n4);
        float4 v1 = has1 ? out4[jx] : make_float4(0.f, 0.f, 0.f, 0.f);
        v0.x = fmaxf(fmaf(v0.x, a.x, b.x), 0.f);
        v0.y = fmaxf(fmaf(v0.y, a.y, b.y), 0.f);
        v0.z = fmaxf(fmaf(v0.z, a.z, b.z), 0.f);
        v0.w = fmaxf(fmaf(v0.w, a.w, b.w), 0.f);
        out4[i] = v0;
        if (has1) {
            v1.x = fmaxf(fmaf(v1.x, a.x, b.x), 0.f);
            v1.y = fmaxf(fmaf(v1.y, a.y, b.y), 0.f);
            v1.z = fmaxf(fmaf(v1.z, a.z, b.z), 0.f);
            v1.w = fmaxf(fmaf(v1.w, a.w, b.w), 0.f);
            out4[jx] = v1;
        }
    }
}

// ---------------------------------------------------------------------------
// Launch. Inputs: x, W, bias, gamma, beta, k_idx, out_idx, num_out.
// ---------------------------------------------------------------------------
extern "C" void kernel_launch(void* const* d_in, const int* in_sizes, int n_in,
                              void* d_out, int out_size)
{
    const float* x     = (const float*)d_in[0];
    const float* W     = (const float*)d_in[1];
    const float* gamma = (const float*)d_in[3];
    const float* beta  = (const float*)d_in[4];
    const int*   kidx  = (const int*)d_in[5];
    const int*   oidx  = (const int*)d_in[6];

    const int n       = in_sizes[0] / C_IN;
    const int total   = out_size;               // num_out * 64
    const int num_out = total / C_OUT;
    const int n4      = total / 4;

    const int smem_bytes = (int)sizeof(ConvSmem);   // ~50 KB (2 CTAs/SM)
    cudaFuncSetAttribute(conv_scatter,
                         cudaFuncAttributeMaxDynamicSharedMemorySize,
                         smem_bytes);

    cudaMemsetAsync(d_out, 0, (size_t)total * sizeof(float), 0);

    const int tiles = (n + TILE - 1) / TILE;
    conv_scatter<<<tiles, 512, smem_bytes>>>(x, W, kidx, oidx, (float*)d_out, n);
    stats_pass<<<1184, 256>>>((const float4*)d_out, n4);
    finalize_stats<<<1, C_OUT>>>(gamma, beta, 1.0f / (float)num_out);
    norm_relu<<<1184, 256>>>((float4*)d_out, n4);
}